// round 1
// baseline (speedup 1.0000x reference)
#include <cuda_runtime.h>
#include <math.h>

#define NN 100000
#define NE 1600000
#define HID 64
#define INC 32

// ---------------- scratch (static device globals; no allocation) ----------------
__device__ float g_bufA[NN * HID];        // GEMM output h
__device__ float g_bufB[NN * HID];        // aggregated x
__device__ float g_ew[4 * NE];            // edge weights, permuted (CSR order), per layer
__device__ int   g_src_perm[NE];          // src node per CSR slot
__device__ int   g_offs[NN + 1];          // CSR offsets by dst
__device__ int   g_cursor[NN];            // degree counters / scatter cursors
__device__ int   g_bsum[128];             // scan block sums

// ---------------- CSR build ----------------
__global__ void k_zero() {
    int i = blockIdx.x * blockDim.x + threadIdx.x;
    if (i < NN) g_cursor[i] = 0;
}

__global__ void k_hist(const int* __restrict__ ei) {
    int e = blockIdx.x * blockDim.x + threadIdx.x;
    if (e < NE) atomicAdd(&g_cursor[ei[NE + e]], 1);   // dst row
}

__global__ void k_scan1() {
    __shared__ int s[1024];
    int tid = threadIdx.x;
    int i = blockIdx.x * 1024 + tid;
    int v = (i < NN) ? g_cursor[i] : 0;
    s[tid] = v;
    __syncthreads();
    for (int off = 1; off < 1024; off <<= 1) {
        int t = (tid >= off) ? s[tid - off] : 0;
        __syncthreads();
        s[tid] += t;
        __syncthreads();
    }
    if (i < NN) g_offs[i] = s[tid] - v;        // exclusive
    if (tid == 1023) g_bsum[blockIdx.x] = s[tid];
}

__global__ void k_scan2(int nblk) {
    if (threadIdx.x == 0) {
        int run = 0;
        for (int b = 0; b < nblk; b++) { int t = g_bsum[b]; g_bsum[b] = run; run += t; }
    }
}

__global__ void k_scan3() {
    int i = blockIdx.x * blockDim.x + threadIdx.x;
    if (i < NN) {
        int o = g_offs[i] + g_bsum[i >> 10];
        g_offs[i] = o;
        g_cursor[i] = o;
    }
    if (i == 0) g_offs[NN] = NE;
}

// ---------------- fused CSR scatter + edge-weight MLP (all 4 layers) ----------------
__global__ void __launch_bounds__(256)
k_scatter_ew(const int* __restrict__ ei, const float* __restrict__ ea,
             const float* __restrict__ ew1, const float* __restrict__ eb1,
             const float* __restrict__ ew2, const float* __restrict__ eb2) {
    __shared__ float s1[4 * 32];   // ew1 [4][2][16]
    __shared__ float sb1[4 * 16];
    __shared__ float s2[4 * 16];
    __shared__ float sb2[4];
    int tx = threadIdx.x;
    if (tx < 128) s1[tx]  = ew1[tx];
    if (tx < 64)  sb1[tx] = eb1[tx];
    if (tx < 64)  s2[tx]  = ew2[tx];
    if (tx < 4)   sb2[tx] = eb2[tx];
    __syncthreads();

    int e = blockIdx.x * blockDim.x + tx;
    if (e >= NE) return;
    int src = ei[e];
    int dst = ei[NE + e];
    float2 a = *(const float2*)&ea[2 * e];
    int pos = atomicAdd(&g_cursor[dst], 1);
    g_src_perm[pos] = src;

    #pragma unroll
    for (int l = 0; l < 4; l++) {
        float z = sb2[l];
        #pragma unroll
        for (int j = 0; j < 16; j++) {
            float h = fmaf(a.x, s1[l * 32 + j], fmaf(a.y, s1[l * 32 + 16 + j], sb1[l * 16 + j]));
            h = fmaxf(h, 0.f);
            z = fmaf(h, s2[l * 16 + j], z);
        }
        g_ew[l * NE + pos] = 1.f / (1.f + expf(-z));
    }
}

// ---------------- node GEMM: h = x @ W + b ----------------
// 16 nodes/block, thread = (node, 4 outputs)
template<int C, bool FROM_BUF>
__global__ void __launch_bounds__(256)
k_gemm(const float* __restrict__ xin, const float* __restrict__ W,
       const float* __restrict__ b) {
    __shared__ float sW[C * 64];
    __shared__ float sB[64];
    __shared__ float sx[16 * C];
    const float* x = FROM_BUF ? (const float*)g_bufB : xin;
    int tx = threadIdx.x;
    for (int i = tx; i < C * 64; i += 256) sW[i] = W[i];
    if (tx < 64) sB[tx] = b[tx];
    int base = blockIdx.x * 16;
    for (int i = tx; i < 16 * C; i += 256) sx[i] = x[base * C + i];
    __syncthreads();

    int jj = (tx & 15) * 4;
    int r  = tx >> 4;
    float4 acc = make_float4(sB[jj], sB[jj + 1], sB[jj + 2], sB[jj + 3]);
    #pragma unroll
    for (int k = 0; k < C; k++) {
        float xk = sx[r * C + k];
        float4 w = *(const float4*)&sW[k * 64 + jj];
        acc.x = fmaf(xk, w.x, acc.x);
        acc.y = fmaf(xk, w.y, acc.y);
        acc.z = fmaf(xk, w.z, acc.z);
        acc.w = fmaf(xk, w.w, acc.w);
    }
    *(float4*)&g_bufA[(base + r) * 64 + jj] = acc;
}

// ---------------- aggregation: x[n] = relu(sum_{e in CSR[n]} ew[e] * h[src[e]]) ----------------
// warp per node; lane owns 2 features (float2)
__global__ void __launch_bounds__(256)
k_agg(int l) {
    int gid  = blockIdx.x * blockDim.x + threadIdx.x;
    int node = gid >> 5;
    int lane = gid & 31;
    if (node >= NN) return;
    int start = g_offs[node], end = g_offs[node + 1];
    const float* __restrict__ ewl = g_ew + (size_t)l * NE;
    float ax = 0.f, ay = 0.f;
    for (int base = start; base < end; base += 32) {
        int idx = base + lane;
        int sl = 0; float wl = 0.f;
        if (idx < end) { sl = g_src_perm[idx]; wl = ewl[idx]; }
        int cnt = min(32, end - base);
        for (int j = 0; j < cnt; j++) {
            int   s = __shfl_sync(0xffffffffu, sl, j);
            float w = __shfl_sync(0xffffffffu, wl, j);
            float2 hv = *(const float2*)&g_bufA[s * 64 + lane * 2];
            ax = fmaf(w, hv.x, ax);
            ay = fmaf(w, hv.y, ay);
        }
    }
    float2 o = make_float2(fmaxf(ax, 0.f), fmaxf(ay, 0.f));
    *(float2*)&g_bufB[node * 64 + lane * 2] = o;
}

// ---------------- regression head ----------------
__global__ void __launch_bounds__(128)
k_head_reg(const float* __restrict__ rh1w, const float* __restrict__ rh1b,
           const float* __restrict__ rh2w, const float* __restrict__ rh2b,
           const float* __restrict__ mw, const float* __restrict__ mb,
           const float* __restrict__ sw, const float* __restrict__ sb,
           float* __restrict__ out) {
    __shared__ float sx[128 * 65];
    __shared__ float s1[64 * 32];
    __shared__ float s2[32 * 16];
    __shared__ float sb1[32], sb2[16], smw[16], ssw[16];
    __shared__ float smb, ssb;
    int tx = threadIdx.x;
    int base = blockIdx.x * 128;
    for (int i = tx; i < 2048; i += 128) s1[i] = rh1w[i];
    for (int i = tx; i < 512;  i += 128) s2[i] = rh2w[i];
    if (tx < 32) sb1[tx] = rh1b[tx];
    if (tx < 16) { sb2[tx] = rh2b[tx]; smw[tx] = mw[tx]; ssw[tx] = sw[tx]; }
    if (tx == 0) { smb = mb[0]; ssb = sb[0]; }
    for (int i = tx; i < 128 * 64; i += 128) {
        int r = i >> 6, k = i & 63;
        int node = base + r;
        sx[r * 65 + k] = (node < NN) ? g_bufB[node * 64 + k] : 0.f;
    }
    __syncthreads();

    float t1[32];
    #pragma unroll
    for (int j = 0; j < 32; j++) t1[j] = sb1[j];
    #pragma unroll
    for (int k = 0; k < 64; k++) {
        float xk = sx[tx * 65 + k];
        #pragma unroll
        for (int j4 = 0; j4 < 8; j4++) {
            float4 w = *(const float4*)&s1[k * 32 + j4 * 4];
            t1[j4 * 4 + 0] = fmaf(xk, w.x, t1[j4 * 4 + 0]);
            t1[j4 * 4 + 1] = fmaf(xk, w.y, t1[j4 * 4 + 1]);
            t1[j4 * 4 + 2] = fmaf(xk, w.z, t1[j4 * 4 + 2]);
            t1[j4 * 4 + 3] = fmaf(xk, w.w, t1[j4 * 4 + 3]);
        }
    }
    float rg[16];
    #pragma unroll
    for (int j = 0; j < 16; j++) rg[j] = sb2[j];
    #pragma unroll
    for (int k = 0; k < 32; k++) {
        float v = fmaxf(t1[k], 0.f);
        #pragma unroll
        for (int j4 = 0; j4 < 4; j4++) {
            float4 w = *(const float4*)&s2[k * 16 + j4 * 4];
            rg[j4 * 4 + 0] = fmaf(v, w.x, rg[j4 * 4 + 0]);
            rg[j4 * 4 + 1] = fmaf(v, w.y, rg[j4 * 4 + 1]);
            rg[j4 * 4 + 2] = fmaf(v, w.z, rg[j4 * 4 + 2]);
            rg[j4 * 4 + 3] = fmaf(v, w.w, rg[j4 * 4 + 3]);
        }
    }
    float mean = smb, z = ssb;
    #pragma unroll
    for (int j = 0; j < 16; j++) {
        float v = fmaxf(rg[j], 0.f);
        mean = fmaf(v, smw[j], mean);
        z    = fmaf(v, ssw[j], z);
    }
    float sp = fmaxf(z, 0.f) + log1pf(expf(-fabsf(z)));   // softplus = logaddexp(z, 0)
    int node = base + tx;
    if (node < NN) { out[node] = mean; out[NN + node] = sp; }
}

// ---------------- classification head ----------------
__global__ void __launch_bounds__(128)
k_head_cls(const float* __restrict__ c1w, const float* __restrict__ c1b,
           const float* __restrict__ c2w, const float* __restrict__ c2b,
           float* __restrict__ out) {
    __shared__ float sx[128 * 65];
    __shared__ float s1[64 * 32];
    __shared__ float s2[32 * 2];
    __shared__ float sb1[32], sb2v[2];
    int tx = threadIdx.x;
    int base = blockIdx.x * 128;
    for (int i = tx; i < 2048; i += 128) s1[i] = c1w[i];
    if (tx < 64) s2[tx] = c2w[tx];
    if (tx < 32) sb1[tx] = c1b[tx];
    if (tx < 2)  sb2v[tx] = c2b[tx];
    for (int i = tx; i < 128 * 64; i += 128) {
        int r = i >> 6, k = i & 63;
        int node = base + r;
        sx[r * 65 + k] = (node < NN) ? g_bufB[node * 64 + k] : 0.f;
    }
    __syncthreads();

    float t1[32];
    #pragma unroll
    for (int j = 0; j < 32; j++) t1[j] = sb1[j];
    #pragma unroll
    for (int k = 0; k < 64; k++) {
        float xk = sx[tx * 65 + k];
        #pragma unroll
        for (int j4 = 0; j4 < 8; j4++) {
            float4 w = *(const float4*)&s1[k * 32 + j4 * 4];
            t1[j4 * 4 + 0] = fmaf(xk, w.x, t1[j4 * 4 + 0]);
            t1[j4 * 4 + 1] = fmaf(xk, w.y, t1[j4 * 4 + 1]);
            t1[j4 * 4 + 2] = fmaf(xk, w.z, t1[j4 * 4 + 2]);
            t1[j4 * 4 + 3] = fmaf(xk, w.w, t1[j4 * 4 + 3]);
        }
    }
    float l0 = sb2v[0], l1 = sb2v[1];
    #pragma unroll
    for (int k = 0; k < 32; k++) {
        float v = fmaxf(t1[k], 0.f);
        l0 = fmaf(v, s2[k * 2 + 0], l0);
        l1 = fmaf(v, s2[k * 2 + 1], l1);
    }
    int node = base + tx;
    if (node < NN) {
        out[2 * NN + 2 * node + 0] = l0;
        out[2 * NN + 2 * node + 1] = l1;
    }
}

// ---------------- launch ----------------
extern "C" void kernel_launch(void* const* d_in, const int* in_sizes, int n_in,
                              void* d_out, int out_size) {
    const float* x    = (const float*)d_in[0];
    const int*   ei   = (const int*)  d_in[1];
    const float* ea   = (const float*)d_in[2];
    const float* W0   = (const float*)d_in[3];
    const float* b0   = (const float*)d_in[4];
    const float* Ws   = (const float*)d_in[5];
    const float* bs   = (const float*)d_in[6];
    const float* ew1  = (const float*)d_in[7];
    const float* eb1  = (const float*)d_in[8];
    const float* ew2  = (const float*)d_in[9];
    const float* eb2  = (const float*)d_in[10];
    const float* rh1w = (const float*)d_in[11];
    const float* rh1b = (const float*)d_in[12];
    const float* rh2w = (const float*)d_in[13];
    const float* rh2b = (const float*)d_in[14];
    const float* mw   = (const float*)d_in[15];
    const float* mb   = (const float*)d_in[16];
    const float* sw   = (const float*)d_in[17];
    const float* sb   = (const float*)d_in[18];
    const float* c1w  = (const float*)d_in[19];
    const float* c1b  = (const float*)d_in[20];
    const float* c2w  = (const float*)d_in[21];
    const float* c2b  = (const float*)d_in[22];
    float* out = (float*)d_out;

    // CSR by dst + per-layer edge weights (permuted)
    k_zero<<<(NN + 255) / 256, 256>>>();
    k_hist<<<(NE + 255) / 256, 256>>>(ei);
    k_scan1<<<98, 1024>>>();
    k_scan2<<<1, 32>>>(98);
    k_scan3<<<(NN + 255) / 256, 256>>>();
    k_scatter_ew<<<(NE + 255) / 256, 256>>>(ei, ea, ew1, eb1, ew2, eb2);

    // layer 0: GEMM (input x, C=32) -> bufA ; aggregate -> bufB
    k_gemm<INC, false><<<NN / 16, 256>>>(x, W0, b0);
    k_agg<<<(NN * 32 + 255) / 256, 256>>>(0);

    // layers 1..3: GEMM (bufB, C=64) -> bufA ; aggregate -> bufB
    for (int l = 1; l < 4; l++) {
        k_gemm<HID, true><<<NN / 16, 256>>>(nullptr, Ws + (size_t)(l - 1) * 4096, bs + (l - 1) * 64);
        k_agg<<<(NN * 32 + 255) / 256, 256>>>(l);
    }

    // heads
    k_head_reg<<<(NN + 127) / 128, 128>>>(rh1w, rh1b, rh2w, rh2b, mw, mb, sw, sb, out);
    k_head_cls<<<(NN + 127) / 128, 128>>>(c1w, c1b, c2w, c2b, out);
}